// round 4
// baseline (speedup 1.0000x reference)
#include <cuda_runtime.h>

// BilinearInterpolation: B=16, H=W=512, C=16 fp32.
// R4: thread-per-quad (R1/R3 memory shape) + smem-staged per-pixel x-math
// (computed once by warps 0-1, broadcast via LDS.128) + packed f32x2 FMA
// (halves FMA-pipe ops). y-side math is block-uniform.

#define BB 16
#define HH 512
#define WW 512

typedef unsigned long long u64;

__device__ __forceinline__ u64 pk2(float v) {
    u64 r; asm("mov.b64 %0, {%1, %1};" : "=l"(r) : "f"(v)); return r;
}
__device__ __forceinline__ u64 mul2(u64 a, u64 b) {
    u64 r; asm("mul.rn.f32x2 %0, %1, %2;" : "=l"(r) : "l"(a), "l"(b)); return r;
}
__device__ __forceinline__ u64 fma2(u64 a, u64 b, u64 c) {
    u64 r; asm("fma.rn.f32x2 %0, %1, %2, %3;" : "=l"(r) : "l"(a), "l"(b), "l"(c)); return r;
}

__global__ void __launch_bounds__(256)
bilinear_x2_kernel(const ulonglong2* __restrict__ X,   // X as 16B quads
                   const float* __restrict__ scale,
                   const float* __restrict__ translate,
                   ulonglong2* __restrict__ out)
{
    __shared__ int4 ent[64];   // per-pixel: {x0*4, x1*4, bits(dx0), bits(dx1)}

    const int t  = threadIdx.x;
    const int oy = blockIdx.y;   // uniform
    const int b  = blockIdx.z;   // uniform

    // ---- uniform batch params ----
    const float s  = __ldg(&scale[b]);
    const float tx = __ldg(&translate[2 * b]);
    const float ty = __ldg(&translate[2 * b + 1]);

    // ---- prologue: 64 threads compute x-side math for the block's 64 pixels ----
    if (t < 64) {
        const int ox = (blockIdx.x << 6) + t;
        const float xc = fmaf((float)ox, 2.0f / 511.0f, -1.0f);
        const float x  = 0.5f * (fmaf(s, xc, tx) + 1.0f) * (float)WW;
        int x0 = (int)x;            // trunc toward zero (matches astype(int32))
        int x1 = x0 + 1;
        x0 = min(max(x0, 0), WW - 1);
        x1 = min(max(x1, 0), WW - 1);
        const float dx1 = (float)x1 - x;
        const float dx0 = x - (float)x0;
        ent[t] = make_int4(x0 << 2, x1 << 2,
                           __float_as_int(dx0), __float_as_int(dx1));
    }

    // ---- uniform y-side math ----
    const float yc = fmaf((float)oy, 2.0f / 511.0f, -1.0f);
    const float y  = 0.5f * (fmaf(s, yc, ty) + 1.0f) * (float)HH;
    int y0 = (int)y;
    int y1 = y0 + 1;
    y0 = min(max(y0, 0), HH - 1);
    y1 = min(max(y1, 0), HH - 1);
    const u64 dy1_2 = pk2((float)y1 - y);
    const u64 dy0_2 = pk2(y - (float)y0);

    const int base = b * (HH * WW * 4);                  // quad index of batch b
    const ulonglong2* __restrict__ R0 = X + base + (y0 << 11);
    const ulonglong2* __restrict__ R1 = X + base + (y1 << 11);

    __syncthreads();

    // ---- main path: one quad per thread ----
    const int4 e = ent[t >> 2];
    const int q  = t & 3;
    const int c0 = e.x + q;
    const int c1 = e.y + q;

    const u64 dx0_2 = pk2(__int_as_float(e.z));
    const u64 dx1_2 = pk2(__int_as_float(e.w));
    const u64 wa = mul2(dx1_2, dy1_2);
    const u64 wb = mul2(dx1_2, dy0_2);
    const u64 wc = mul2(dx0_2, dy1_2);
    const u64 wd = mul2(dx0_2, dy0_2);

    const ulonglong2 pa = __ldg(R0 + c0);
    const ulonglong2 pb = __ldg(R1 + c0);
    const ulonglong2 pc = __ldg(R0 + c1);
    const ulonglong2 pd = __ldg(R1 + c1);

    ulonglong2 o;
    o.x = fma2(wa, pa.x, fma2(wb, pb.x, fma2(wc, pc.x, mul2(wd, pd.x))));
    o.y = fma2(wa, pa.y, fma2(wb, pb.y, fma2(wc, pc.y, mul2(wd, pd.y))));

    const int obase = ((b * HH + oy) << 11) + (blockIdx.x << 8);
    out[obase + t] = o;
}

extern "C" void kernel_launch(void* const* d_in, const int* in_sizes, int n_in,
                              void* d_out, int out_size)
{
    const float* X         = (const float*)d_in[0];
    const float* scale     = (const float*)d_in[1];
    const float* translate = (const float*)d_in[2];

    dim3 grid(WW / 64, HH, BB);   // (8, 512, 16)
    bilinear_x2_kernel<<<grid, 256>>>((const ulonglong2*)X, scale, translate,
                                      (ulonglong2*)d_out);
}

// round 6
// speedup vs baseline: 1.1759x; 1.1759x over previous
#include <cuda_runtime.h>

// BilinearInterpolation: B=16, H=W=512, C=16 fp32.
// R6: two adjacent output rows per block with uniform-branch gather dedup.
// FIX vs R5: branch 1 now requires BOTH clamped row pairs equal
// (y0b==y0a && y1b==y1a); clamp-straddle cases fall through to branch 2/3.

#define BB 16
#define HH 512
#define WW 512

typedef unsigned long long u64;

__device__ __forceinline__ u64 pk2(float v) {
    u64 r; asm("mov.b64 %0, {%1, %1};" : "=l"(r) : "f"(v)); return r;
}
__device__ __forceinline__ u64 mul2(u64 a, u64 b) {
    u64 r; asm("mul.rn.f32x2 %0, %1, %2;" : "=l"(r) : "l"(a), "l"(b)); return r;
}
__device__ __forceinline__ u64 fma2(u64 a, u64 b, u64 c) {
    u64 r; asm("fma.rn.f32x2 %0, %1, %2, %3;" : "=l"(r) : "l"(a), "l"(b), "l"(c)); return r;
}

__device__ __forceinline__ ulonglong2 blend(u64 wa, u64 wb, u64 wc, u64 wd,
                                            ulonglong2 pa, ulonglong2 pb,
                                            ulonglong2 pc, ulonglong2 pd)
{
    ulonglong2 o;
    o.x = fma2(wa, pa.x, fma2(wb, pb.x, fma2(wc, pc.x, mul2(wd, pd.x))));
    o.y = fma2(wa, pa.y, fma2(wb, pb.y, fma2(wc, pc.y, mul2(wd, pd.y))));
    return o;
}

__global__ void __launch_bounds__(256)
bilinear_2row_kernel(const ulonglong2* __restrict__ X,
                     const float* __restrict__ scale,
                     const float* __restrict__ translate,
                     ulonglong2* __restrict__ out)
{
    const int t  = threadIdx.x;
    const int b  = blockIdx.z;          // uniform
    const int oyA = blockIdx.y << 1;    // uniform
    const int oyB = oyA + 1;

    // ---- uniform batch params + y-side math for both rows ----
    const float s  = __ldg(&scale[b]);
    const float tx = __ldg(&translate[2 * b]);
    const float ty = __ldg(&translate[2 * b + 1]);

    const float yA = 0.5f * (fmaf(s, fmaf((float)oyA, 2.0f / 511.0f, -1.0f), ty) + 1.0f) * (float)HH;
    const float yB = 0.5f * (fmaf(s, fmaf((float)oyB, 2.0f / 511.0f, -1.0f), ty) + 1.0f) * (float)HH;

    int y0a = (int)yA, y0b = (int)yB;            // trunc toward zero
    int y1a = y0a + 1, y1b = y0b + 1;
    y0a = min(max(y0a, 0), HH - 1);
    y1a = min(max(y1a, 0), HH - 1);
    y0b = min(max(y0b, 0), HH - 1);
    y1b = min(max(y1b, 0), HH - 1);

    const u64 dy1A = pk2((float)y1a - yA), dy0A = pk2(yA - (float)y0a);
    const u64 dy1B = pk2((float)y1b - yB), dy0B = pk2(yB - (float)y0b);

    const int base = b * (HH * WW * 4);          // quad index of batch b
    const ulonglong2* __restrict__ RA0 = X + base + (y0a << 11);
    const ulonglong2* __restrict__ RA1 = X + base + (y1a << 11);
    const ulonglong2* __restrict__ RB0 = X + base + (y0b << 11);
    const ulonglong2* __restrict__ RB1 = X + base + (y1b << 11);

    // ---- per-thread x-side math (shared by both output rows) ----
    const int q  = t & 3;
    const int ox = (blockIdx.x << 6) + (t >> 2);
    const float xc = fmaf((float)ox, 2.0f / 511.0f, -1.0f);
    const float x  = 0.5f * (fmaf(s, xc, tx) + 1.0f) * (float)WW;
    int x0 = (int)x;
    int x1 = x0 + 1;
    x0 = min(max(x0, 0), WW - 1);
    x1 = min(max(x1, 0), WW - 1);
    const u64 dx1 = pk2((float)x1 - x);
    const u64 dx0 = pk2(x - (float)x0);

    const int c0 = (x0 << 2) + q;
    const int c1 = (x1 << 2) + q;

    const u64 waA = mul2(dx1, dy1A), wbA = mul2(dx1, dy0A);
    const u64 wcA = mul2(dx0, dy1A), wdA = mul2(dx0, dy0A);
    const u64 waB = mul2(dx1, dy1B), wbB = mul2(dx1, dy0B);
    const u64 wcB = mul2(dx0, dy1B), wdB = mul2(dx0, dy0B);

    ulonglong2 oA, oB;

    // Uniform branches (all y's are block-uniform).
    if (y0b == y0a && y1b == y1a) {
        // both outputs use identical row pair: 4 loads serve 2 outputs
        const ulonglong2 p00 = __ldg(RA0 + c0);
        const ulonglong2 p01 = __ldg(RA0 + c1);
        const ulonglong2 p10 = __ldg(RA1 + c0);
        const ulonglong2 p11 = __ldg(RA1 + c1);
        oA = blend(waA, wbA, wcA, wdA, p00, p10, p01, p11);
        oB = blend(waB, wbB, wcB, wdB, p00, p10, p01, p11);
    } else if (y0b == y1a) {
        // B's top row == A's bottom row: 6 loads serve 2 outputs
        // (covers clamp-straddle cases: y1b may equal y0b, still correct)
        const ulonglong2 r0c0 = __ldg(RA0 + c0);
        const ulonglong2 r0c1 = __ldg(RA0 + c1);
        const ulonglong2 r1c0 = __ldg(RA1 + c0);
        const ulonglong2 r1c1 = __ldg(RA1 + c1);
        const ulonglong2 r2c0 = __ldg(RB1 + c0);
        const ulonglong2 r2c1 = __ldg(RB1 + c1);
        oA = blend(waA, wbA, wcA, wdA, r0c0, r1c0, r0c1, r1c1);
        oB = blend(waB, wbB, wcB, wdB, r1c0, r2c0, r1c1, r2c1);
    } else {
        // fully general fallback: 8 independent loads
        const ulonglong2 paA = __ldg(RA0 + c0);
        const ulonglong2 pbA = __ldg(RA1 + c0);
        const ulonglong2 pcA = __ldg(RA0 + c1);
        const ulonglong2 pdA = __ldg(RA1 + c1);
        oA = blend(waA, wbA, wcA, wdA, paA, pbA, pcA, pdA);
        const ulonglong2 paB = __ldg(RB0 + c0);
        const ulonglong2 pbB = __ldg(RB1 + c0);
        const ulonglong2 pcB = __ldg(RB0 + c1);
        const ulonglong2 pdB = __ldg(RB1 + c1);
        oB = blend(waB, wbB, wcB, wdB, paB, pbB, pcB, pdB);
    }

    const int obaseA = ((b * HH + oyA) << 11) + (blockIdx.x << 8) + t;
    out[obaseA]        = oA;
    out[obaseA + 2048] = oB;   // next row: +W*4 quads
}

extern "C" void kernel_launch(void* const* d_in, const int* in_sizes, int n_in,
                              void* d_out, int out_size)
{
    const float* X         = (const float*)d_in[0];
    const float* scale     = (const float*)d_in[1];
    const float* translate = (const float*)d_in[2];

    dim3 grid(WW / 64, HH / 2, BB);   // (8, 256, 16) = 32768 blocks
    bilinear_2row_kernel<<<grid, 256>>>((const ulonglong2*)X, scale, translate,
                                        (ulonglong2*)d_out);
}

// round 7
// speedup vs baseline: 1.3222x; 1.1243x over previous
#include <cuda_runtime.h>

// BilinearInterpolation: B=16, H=W=512, C=16 fp32.
// R7: FOUR adjacent output rows per block with a rolling 2-row register cache.
// y-rows are block-uniform & monotone => reuse/shift/reload decided by uniform
// branches. Thread-per-quad memory shape, f32x2 packed FMA, no smem.

#define BB 16
#define HH 512
#define WW 512
#define ROWS 4

typedef unsigned long long u64;

__device__ __forceinline__ u64 pk2(float v) {
    u64 r; asm("mov.b64 %0, {%1, %1};" : "=l"(r) : "f"(v)); return r;
}
__device__ __forceinline__ u64 mul2(u64 a, u64 b) {
    u64 r; asm("mul.rn.f32x2 %0, %1, %2;" : "=l"(r) : "l"(a), "l"(b)); return r;
}
__device__ __forceinline__ u64 fma2(u64 a, u64 b, u64 c) {
    u64 r; asm("fma.rn.f32x2 %0, %1, %2, %3;" : "=l"(r) : "l"(a), "l"(b), "l"(c)); return r;
}

__global__ void __launch_bounds__(256)
bilinear_4row_kernel(const ulonglong2* __restrict__ X,
                     const float* __restrict__ scale,
                     const float* __restrict__ translate,
                     ulonglong2* __restrict__ out)
{
    const int t   = threadIdx.x;
    const int b   = blockIdx.z;            // uniform
    const int oy0 = blockIdx.y * ROWS;     // uniform

    // ---- uniform batch params ----
    const float s  = __ldg(&scale[b]);
    const float tx = __ldg(&translate[2 * b]);
    const float ty = __ldg(&translate[2 * b + 1]);

    // ---- per-thread x-side math (shared by all ROWS outputs) ----
    const int q  = t & 3;
    const int ox = (blockIdx.x << 6) + (t >> 2);
    const float xc = fmaf((float)ox, 2.0f / 511.0f, -1.0f);
    const float x  = 0.5f * (fmaf(s, xc, tx) + 1.0f) * (float)WW;
    int x0 = (int)x;            // trunc toward zero (matches astype(int32))
    int x1 = x0 + 1;
    x0 = min(max(x0, 0), WW - 1);
    x1 = min(max(x1, 0), WW - 1);
    const u64 dx1 = pk2((float)x1 - x);
    const u64 dx0 = pk2(x - (float)x0);

    const int c0 = (x0 << 2) + q;
    const int c1 = (x1 << 2) + q;

    const ulonglong2* __restrict__ Xb = X + b * (HH * WW * 4);
    const int obase = ((b * HH + oy0) << 11) + (blockIdx.x << 8) + t;

    // rolling 2-row cache (register resident)
    int cur0 = -9, cur1 = -9;
    ulonglong2 v0c0, v0c1, v1c0, v1c1;

    #pragma unroll
    for (int r = 0; r < ROWS; ++r) {
        // ---- uniform y-side math for this output row ----
        const float yc = fmaf((float)(oy0 + r), 2.0f / 511.0f, -1.0f);
        const float y  = 0.5f * (fmaf(s, yc, ty) + 1.0f) * (float)HH;
        int y0 = (int)y;
        int y1 = y0 + 1;
        y0 = min(max(y0, 0), HH - 1);
        y1 = min(max(y1, 0), HH - 1);
        const u64 dy1 = pk2((float)y1 - y);
        const u64 dy0 = pk2(y - (float)y0);

        // ---- uniform row-cache update ----
        if (y0 == cur0 && y1 == cur1) {
            // full reuse: 0 loads
        } else if (y0 == cur1) {
            // shift: reuse hi as lo, load new hi (also covers top-clamp y1==y0)
            v0c0 = v1c0; v0c1 = v1c1;
            const ulonglong2* R1 = Xb + (y1 << 11);
            v1c0 = __ldg(R1 + c0);
            v1c1 = __ldg(R1 + c1);
            cur0 = y0; cur1 = y1;
        } else {
            // load both rows
            const ulonglong2* R0 = Xb + (y0 << 11);
            const ulonglong2* R1 = Xb + (y1 << 11);
            v0c0 = __ldg(R0 + c0);
            v0c1 = __ldg(R0 + c1);
            v1c0 = __ldg(R1 + c0);
            v1c1 = __ldg(R1 + c1);
            cur0 = y0; cur1 = y1;
        }

        // ---- blend + store ----
        const u64 wa = mul2(dx1, dy1);
        const u64 wb = mul2(dx1, dy0);
        const u64 wc = mul2(dx0, dy1);
        const u64 wd = mul2(dx0, dy0);

        ulonglong2 o;
        o.x = fma2(wa, v0c0.x, fma2(wb, v1c0.x, fma2(wc, v0c1.x, mul2(wd, v1c1.x))));
        o.y = fma2(wa, v0c0.y, fma2(wb, v1c0.y, fma2(wc, v0c1.y, mul2(wd, v1c1.y))));

        out[obase + (r << 11)] = o;
    }
}

extern "C" void kernel_launch(void* const* d_in, const int* in_sizes, int n_in,
                              void* d_out, int out_size)
{
    const float* X         = (const float*)d_in[0];
    const float* scale     = (const float*)d_in[1];
    const float* translate = (const float*)d_in[2];

    dim3 grid(WW / 64, HH / ROWS, BB);   // (8, 128, 16) = 16384 blocks
    bilinear_4row_kernel<<<grid, 256>>>((const ulonglong2*)X, scale, translate,
                                        (ulonglong2*)d_out);
}

// round 8
// speedup vs baseline: 1.4076x; 1.0647x over previous
#include <cuda_runtime.h>

// BilinearInterpolation: B=16, H=W=512, C=16 fp32.
// R8: EIGHT adjacent output rows per block. Rolling cache now holds the
// HORIZONTAL interpolants h = dx1*p(x0) + dx0*p(x1) of the two active input
// rows (computed once per loaded row), so each output is just
// o = dy1*h0 + dy0*h1 (2 f32x2 ops per half). Uniform reuse/shift/reload
// branches as in R7. Thread-per-quad shape, f32x2 packed math.

#define BB 16
#define HH 512
#define WW 512
#define ROWS 8

typedef unsigned long long u64;

__device__ __forceinline__ u64 pk2(float v) {
    u64 r; asm("mov.b64 %0, {%1, %1};" : "=l"(r) : "f"(v)); return r;
}
__device__ __forceinline__ u64 mul2(u64 a, u64 b) {
    u64 r; asm("mul.rn.f32x2 %0, %1, %2;" : "=l"(r) : "l"(a), "l"(b)); return r;
}
__device__ __forceinline__ u64 fma2(u64 a, u64 b, u64 c) {
    u64 r; asm("fma.rn.f32x2 %0, %1, %2, %3;" : "=l"(r) : "l"(a), "l"(b), "l"(c)); return r;
}

struct H2 { u64 x, y; };   // horizontal interpolant of one input row (4 floats)

__device__ __forceinline__ H2 hload(const ulonglong2* __restrict__ row,
                                    int c0, int c1, u64 dx0, u64 dx1)
{
    const ulonglong2 p0 = __ldg(row + c0);
    const ulonglong2 p1 = __ldg(row + c1);
    H2 h;
    h.x = fma2(dx1, p0.x, mul2(dx0, p1.x));
    h.y = fma2(dx1, p0.y, mul2(dx0, p1.y));
    return h;
}

__global__ void __launch_bounds__(256)
bilinear_8row_kernel(const ulonglong2* __restrict__ X,
                     const float* __restrict__ scale,
                     const float* __restrict__ translate,
                     ulonglong2* __restrict__ out)
{
    const int t   = threadIdx.x;
    const int b   = blockIdx.z;            // uniform
    const int oy0 = blockIdx.y * ROWS;     // uniform

    // ---- uniform batch params ----
    const float s  = __ldg(&scale[b]);
    const float tx = __ldg(&translate[2 * b]);
    const float ty = __ldg(&translate[2 * b + 1]);

    // ---- per-thread x-side math (shared by all ROWS outputs) ----
    const int q  = t & 3;
    const int ox = (blockIdx.x << 6) + (t >> 2);
    const float xc = fmaf((float)ox, 2.0f / 511.0f, -1.0f);
    const float x  = 0.5f * (fmaf(s, xc, tx) + 1.0f) * (float)WW;
    int x0 = (int)x;            // trunc toward zero (matches astype(int32))
    int x1 = x0 + 1;
    x0 = min(max(x0, 0), WW - 1);
    x1 = min(max(x1, 0), WW - 1);
    const u64 dx1 = pk2((float)x1 - x);
    const u64 dx0 = pk2(x - (float)x0);

    const int c0 = (x0 << 2) + q;
    const int c1 = (x1 << 2) + q;

    const ulonglong2* __restrict__ Xb = X + b * (HH * WW * 4);
    const int obase = ((b * HH + oy0) << 11) + (blockIdx.x << 8) + t;

    // rolling 2-row cache of horizontal interpolants
    int cur0 = -9, cur1 = -9;
    H2 h0, h1;

    #pragma unroll
    for (int r = 0; r < ROWS; ++r) {
        // ---- uniform y-side math for this output row ----
        const float yc = fmaf((float)(oy0 + r), 2.0f / 511.0f, -1.0f);
        const float y  = 0.5f * (fmaf(s, yc, ty) + 1.0f) * (float)HH;
        int y0 = (int)y;
        int y1 = y0 + 1;
        y0 = min(max(y0, 0), HH - 1);
        y1 = min(max(y1, 0), HH - 1);
        const u64 dy1 = pk2((float)y1 - y);
        const u64 dy0 = pk2(y - (float)y0);

        // ---- uniform row-cache update ----
        if (y0 == cur0 && y1 == cur1) {
            // full reuse: 0 loads
        } else if (y0 == cur1) {
            // shift: reuse hi as lo, load new hi (covers clamp-straddle too)
            h0 = h1;
            h1 = hload(Xb + (y1 << 11), c0, c1, dx0, dx1);
            cur0 = y0; cur1 = y1;
        } else {
            h0 = hload(Xb + (y0 << 11), c0, c1, dx0, dx1);
            h1 = hload(Xb + (y1 << 11), c0, c1, dx0, dx1);
            cur0 = y0; cur1 = y1;
        }

        // ---- vertical blend + store ----
        ulonglong2 o;
        o.x = fma2(dy1, h0.x, mul2(dy0, h1.x));
        o.y = fma2(dy1, h0.y, mul2(dy0, h1.y));

        out[obase + (r << 11)] = o;
    }
}

extern "C" void kernel_launch(void* const* d_in, const int* in_sizes, int n_in,
                              void* d_out, int out_size)
{
    const float* X         = (const float*)d_in[0];
    const float* scale     = (const float*)d_in[1];
    const float* translate = (const float*)d_in[2];

    dim3 grid(WW / 64, HH / ROWS, BB);   // (8, 64, 16) = 8192 blocks
    bilinear_8row_kernel<<<grid, 256>>>((const ulonglong2*)X, scale, translate,
                                        (ulonglong2*)d_out);
}

// round 9
// speedup vs baseline: 1.4663x; 1.0417x over previous
#include <cuda_runtime.h>

// BilinearInterpolation: B=16, H=W=512, C=16 fp32.
// R9: SIXTEEN adjacent output rows per block, rolling 2-row cache of
// horizontal interpolants (R8 structure). Streaming stores (st.global.cs)
// keep L2 reserved for the input rows. Thread-per-quad, f32x2 packed math.

#define BB 16
#define HH 512
#define WW 512
#define ROWS 16

typedef unsigned long long u64;

__device__ __forceinline__ u64 pk2(float v) {
    u64 r; asm("mov.b64 %0, {%1, %1};" : "=l"(r) : "f"(v)); return r;
}
__device__ __forceinline__ u64 mul2(u64 a, u64 b) {
    u64 r; asm("mul.rn.f32x2 %0, %1, %2;" : "=l"(r) : "l"(a), "l"(b)); return r;
}
__device__ __forceinline__ u64 fma2(u64 a, u64 b, u64 c) {
    u64 r; asm("fma.rn.f32x2 %0, %1, %2, %3;" : "=l"(r) : "l"(a), "l"(b), "l"(c)); return r;
}
__device__ __forceinline__ void stcs(ulonglong2* p, u64 lo, u64 hi) {
    asm volatile("st.global.cs.v2.u64 [%0], {%1, %2};"
                 :: "l"(p), "l"(lo), "l"(hi) : "memory");
}

struct H2 { u64 x, y; };   // horizontal interpolant of one input row (4 floats)

__device__ __forceinline__ H2 hload(const ulonglong2* __restrict__ row,
                                    int c0, int c1, u64 dx0, u64 dx1)
{
    const ulonglong2 p0 = __ldg(row + c0);
    const ulonglong2 p1 = __ldg(row + c1);
    H2 h;
    h.x = fma2(dx1, p0.x, mul2(dx0, p1.x));
    h.y = fma2(dx1, p0.y, mul2(dx0, p1.y));
    return h;
}

__global__ void __launch_bounds__(256)
bilinear_16row_kernel(const ulonglong2* __restrict__ X,
                      const float* __restrict__ scale,
                      const float* __restrict__ translate,
                      ulonglong2* __restrict__ out)
{
    const int t   = threadIdx.x;
    const int b   = blockIdx.z;            // uniform
    const int oy0 = blockIdx.y * ROWS;     // uniform

    // ---- uniform batch params ----
    const float s  = __ldg(&scale[b]);
    const float tx = __ldg(&translate[2 * b]);
    const float ty = __ldg(&translate[2 * b + 1]);

    // ---- per-thread x-side math (shared by all ROWS outputs) ----
    const int q  = t & 3;
    const int ox = (blockIdx.x << 6) + (t >> 2);
    const float xc = fmaf((float)ox, 2.0f / 511.0f, -1.0f);
    const float x  = 0.5f * (fmaf(s, xc, tx) + 1.0f) * (float)WW;
    int x0 = (int)x;            // trunc toward zero (matches astype(int32))
    int x1 = x0 + 1;
    x0 = min(max(x0, 0), WW - 1);
    x1 = min(max(x1, 0), WW - 1);
    const u64 dx1 = pk2((float)x1 - x);
    const u64 dx0 = pk2(x - (float)x0);

    const int c0 = (x0 << 2) + q;
    const int c1 = (x1 << 2) + q;

    const ulonglong2* __restrict__ Xb = X + b * (HH * WW * 4);
    ulonglong2* __restrict__ O = out + ((b * HH + oy0) << 11) + (blockIdx.x << 8) + t;

    // rolling 2-row cache of horizontal interpolants
    int cur0 = -9, cur1 = -9;
    H2 h0, h1;

    #pragma unroll
    for (int r = 0; r < ROWS; ++r) {
        // ---- uniform y-side math for this output row ----
        const float yc = fmaf((float)(oy0 + r), 2.0f / 511.0f, -1.0f);
        const float y  = 0.5f * (fmaf(s, yc, ty) + 1.0f) * (float)HH;
        int y0 = (int)y;
        int y1 = y0 + 1;
        y0 = min(max(y0, 0), HH - 1);
        y1 = min(max(y1, 0), HH - 1);
        const u64 dy1 = pk2((float)y1 - y);
        const u64 dy0 = pk2(y - (float)y0);

        // ---- uniform row-cache update ----
        if (y0 == cur0 && y1 == cur1) {
            // full reuse: 0 loads
        } else if (y0 == cur1) {
            // shift: reuse hi as lo, load new hi (covers clamp-straddle too)
            h0 = h1;
            h1 = hload(Xb + (y1 << 11), c0, c1, dx0, dx1);
            cur0 = y0; cur1 = y1;
        } else {
            h0 = hload(Xb + (y0 << 11), c0, c1, dx0, dx1);
            h1 = hload(Xb + (y1 << 11), c0, c1, dx0, dx1);
            cur0 = y0; cur1 = y1;
        }

        // ---- vertical blend + streaming store ----
        const u64 olo = fma2(dy1, h0.x, mul2(dy0, h1.x));
        const u64 ohi = fma2(dy1, h0.y, mul2(dy0, h1.y));
        stcs(O + (r << 11), olo, ohi);
    }
}

extern "C" void kernel_launch(void* const* d_in, const int* in_sizes, int n_in,
                              void* d_out, int out_size)
{
    const float* X         = (const float*)d_in[0];
    const float* scale     = (const float*)d_in[1];
    const float* translate = (const float*)d_in[2];

    dim3 grid(WW / 64, HH / ROWS, BB);   // (8, 32, 16) = 4096 blocks
    bilinear_16row_kernel<<<grid, 256>>>((const ulonglong2*)X, scale, translate,
                                         (ulonglong2*)d_out);
}